// round 16
// baseline (speedup 1.0000x reference)
#include <cuda_runtime.h>
#include <cuda_bf16.h>
#include <math.h>

#define MAX_N 100000
#define D_IN 32
#define D_H 64

// Scratch (device globals — accessed ONLY from device code; never passed as
// kernel arguments from host, where the symbol would resolve to the host
// shadow address).
__device__ float g_hs1[MAX_N * D_H];   // (x@W1)*dinv
__device__ float g_acc1[MAX_N * D_H];  // layer-1 scatter accumulator
__device__ float g_hs2[MAX_N * D_H];   // (h1f@W2)*dinv
__device__ float g_acc2[MAX_N * D_H];  // layer-2 scatter accumulator
__device__ int   g_deg[MAX_N];
__device__ float g_dinv[MAX_N];

// ---------------------------------------------------------------------------
__global__ void zero_kernel(int N) {
    int stride = gridDim.x * blockDim.x;
    int i = blockIdx.x * blockDim.x + threadIdx.x;
    int total = N * D_H;
    for (int j = i; j < total; j += stride) {
        g_acc1[j] = 0.0f;
        g_acc2[j] = 0.0f;
    }
    for (int j = i; j < N; j += stride) g_deg[j] = 0;
}

// Degree of each dst node (self-loop contributes +1 in dinv_kernel)
__global__ void deg_kernel(const int* __restrict__ ei, int E, int N) {
    int stride = gridDim.x * blockDim.x;
    for (int e = blockIdx.x * blockDim.x + threadIdx.x; e < E; e += stride) {
        unsigned dst = (unsigned)ei[E + e];
        if (dst < (unsigned)N) atomicAdd(&g_deg[dst], 1);
    }
}

__global__ void dinv_kernel(int N) {
    int i = blockIdx.x * blockDim.x + threadIdx.x;
    if (i < N) g_dinv[i] = rsqrtf((float)g_deg[i] + 1.0f);
}

// ---------------------------------------------------------------------------
// hs1 = (x @ W1) * dinv[row]     x:[N,32]  W1:[32,64]
__global__ __launch_bounds__(256) void gemm1_kernel(
    const float* __restrict__ x, const float* __restrict__ W1, int N)
{
    __shared__ float Ws[D_IN * D_H];
    __shared__ float xs[4][D_IN];

    int t = threadIdx.x;
    for (int i = t; i < D_IN * D_H; i += 256) Ws[i] = W1[i];

    int row0 = blockIdx.x * 4;
    for (int i = t; i < 4 * D_IN; i += 256) {
        int r = i / D_IN, c = i % D_IN;
        int gr = row0 + r;
        xs[r][c] = (gr < N) ? x[(size_t)gr * D_IN + c] : 0.0f;
    }
    __syncthreads();

    int r = t / D_H, c = t % D_H;
    int row = row0 + r;
    if (row < N) {
        float s = 0.0f;
        #pragma unroll
        for (int k = 0; k < D_IN; k++) s = fmaf(xs[r][k], Ws[k * D_H + c], s);
        g_hs1[(size_t)row * D_H + c] = s * g_dinv[row];
    }
}

// ---------------------------------------------------------------------------
// Scatter: acc[dst] += hs[src].  16 lanes/edge, float4 vector reduction.
// which: 1 -> (g_hs1, g_acc1), 2 -> (g_hs2, g_acc2). Symbols resolved in
// DEVICE code so the addresses are the real device-memory copies.
__global__ __launch_bounds__(256) void scatter_kernel(
    const int* __restrict__ ei, int E, int N, int which)
{
    const float* hs = (which == 1) ? g_hs1 : g_hs2;
    float*       acc = (which == 1) ? g_acc1 : g_acc2;

    long long tid = (long long)blockIdx.x * blockDim.x + threadIdx.x;
    int edge = (int)(tid >> 4);
    int lane = (int)(tid & 15);
    if (edge >= E) return;

    unsigned src = (unsigned)ei[edge];
    unsigned dst = (unsigned)ei[E + edge];
    if (src >= (unsigned)N || dst >= (unsigned)N) return;

    const float4* sp = (const float4*)(hs + (size_t)src * D_H) + lane;
    float4 v = *sp;
    float* dp = acc + (size_t)dst * D_H + lane * 4;
    asm volatile("red.global.add.v4.f32 [%0], {%1,%2,%3,%4};"
                 :: "l"(dp), "f"(v.x), "f"(v.y), "f"(v.z), "f"(v.w)
                 : "memory");
}

// ---------------------------------------------------------------------------
// Fused: h1f = relu(dinv*(acc1 + hs1) + b1)   (self-loop term = +hs1)
//        hs2 = (h1f @ W2) * dinv              W2:[64,64]
__global__ __launch_bounds__(256) void gemm2_kernel(
    const float* __restrict__ W2, const float* __restrict__ b1, int N)
{
    __shared__ float Ws[D_H * D_H];
    __shared__ float hsrow[4][D_H];

    int t = threadIdx.x;
    for (int i = t; i < D_H * D_H; i += 256) Ws[i] = W2[i];

    int row0 = blockIdx.x * 4;
    int r = t / D_H, c = t % D_H;
    int row = row0 + r;

    float di = (row < N) ? g_dinv[row] : 0.0f;
    if (row < N) {
        size_t off = (size_t)row * D_H + c;
        float h = di * (g_acc1[off] + g_hs1[off]) + b1[c];
        hsrow[r][c] = fmaxf(h, 0.0f);
    }
    __syncthreads();

    if (row < N) {
        float s = 0.0f;
        #pragma unroll
        for (int k = 0; k < D_H; k++) s = fmaf(hsrow[r][k], Ws[k * D_H + c], s);
        g_hs2[(size_t)row * D_H + c] = s * di;
    }
}

// ---------------------------------------------------------------------------
// Fused: h2f = relu(dinv*(acc2 + hs2) + b2);  out = sigmoid(h2f . Wo + bo)
// One warp per node; lane handles cols {lane, lane+32}.
__global__ __launch_bounds__(256) void out_kernel(
    const float* __restrict__ b2, const float* __restrict__ Wo,
    const float* __restrict__ bo, float* __restrict__ out, int N)
{
    int warp = (blockIdx.x * blockDim.x + threadIdx.x) >> 5;
    int lane = threadIdx.x & 31;
    if (warp >= N) return;

    float di = g_dinv[warp];
    size_t base = (size_t)warp * D_H;

    float s = 0.0f;
    #pragma unroll
    for (int half = 0; half < 2; half++) {
        int c = lane + half * 32;
        float h = di * (g_acc2[base + c] + g_hs2[base + c]) + b2[c];
        h = fmaxf(h, 0.0f);
        s = fmaf(h, Wo[c], s);
    }
    #pragma unroll
    for (int o = 16; o > 0; o >>= 1) s += __shfl_down_sync(0xffffffffu, s, o);

    if (lane == 0) {
        float z = s + bo[0];
        out[warp] = 1.0f / (1.0f + expf(-z));
    }
}

// ---------------------------------------------------------------------------
extern "C" void kernel_launch(void* const* d_in, const int* in_sizes, int n_in,
                              void* d_out, int out_size)
{
    const float* x  = (const float*)d_in[0];
    const int*   ei = (const int*)d_in[1];
    const float* W1 = (const float*)d_in[2];
    const float* b1 = (const float*)d_in[3];
    const float* W2 = (const float*)d_in[4];
    const float* b2 = (const float*)d_in[5];
    const float* Wo = (const float*)d_in[6];
    const float* bo = (const float*)d_in[7];
    float* out = (float*)d_out;

    int N = in_sizes[0] / D_IN;
    int E = in_sizes[1] / 2;

    zero_kernel<<<2048, 256>>>(N);
    deg_kernel<<<2048, 256>>>(ei, E, N);
    dinv_kernel<<<(N + 255) / 256, 256>>>(N);

    gemm1_kernel<<<(N + 3) / 4, 256>>>(x, W1, N);

    long long sthreads = (long long)E * 16;
    int sblocks = (int)((sthreads + 255) / 256);
    scatter_kernel<<<sblocks, 256>>>(ei, E, N, 1);

    gemm2_kernel<<<(N + 3) / 4, 256>>>(W2, b1, N);

    scatter_kernel<<<sblocks, 256>>>(ei, E, N, 2);

    out_kernel<<<(N * 32 + 255) / 256, 256>>>(b2, Wo, bo, out, N);
}

// round 17
// speedup vs baseline: 1.0389x; 1.0389x over previous
#include <cuda_runtime.h>
#include <cuda_bf16.h>
#include <math.h>

#define MAX_N 100000
#define D_IN 32
#define D_H 64

// Scratch (device globals — resolved ONLY inside device code; host passes
// selector ints, never these symbols).
__device__ float g_hs1[MAX_N * D_H];   // (x@W1)*dinv
__device__ float g_acc1[MAX_N * D_H];  // layer-1 scatter accumulator
__device__ float g_hs2[MAX_N * D_H];   // (h1f@W2)*dinv
__device__ float g_acc2[MAX_N * D_H];  // layer-2 scatter accumulator
__device__ int   g_deg[MAX_N];
__device__ float g_dinv[MAX_N];

// ---------------------------------------------------------------------------
__global__ void zero_kernel(int N) {
    int stride = gridDim.x * blockDim.x;
    int i = blockIdx.x * blockDim.x + threadIdx.x;
    int total = N * D_H;
    for (int j = i; j < total; j += stride) {
        g_acc1[j] = 0.0f;
        g_acc2[j] = 0.0f;
    }
    for (int j = i; j < N; j += stride) g_deg[j] = 0;
}

__global__ void deg_kernel(const int* __restrict__ ei, int E, int N) {
    int stride = gridDim.x * blockDim.x;
    for (int e = blockIdx.x * blockDim.x + threadIdx.x; e < E; e += stride) {
        unsigned dst = (unsigned)ei[E + e];
        if (dst < (unsigned)N) atomicAdd(&g_deg[dst], 1);
    }
}

__global__ void dinv_kernel(int N) {
    int i = blockIdx.x * blockDim.x + threadIdx.x;
    if (i < N) g_dinv[i] = rsqrtf((float)g_deg[i] + 1.0f);
}

// ---------------------------------------------------------------------------
// hs1 = (x @ W1) * dinv[row].   Register-tiled: 32 rows/block, 8 threads/row,
// each thread computes 8 adjacent columns.
__global__ __launch_bounds__(256) void gemm1_kernel(
    const float* __restrict__ x, const float* __restrict__ W1, int N)
{
    __shared__ float Ws[D_IN * D_H];     // 8 KB
    __shared__ float xs[32][D_IN + 1];   // +1 pad vs bank conflicts

    int t = threadIdx.x;
    // Load W1 via float4
    const float4* W4 = (const float4*)W1;
    float4* Ws4 = (float4*)Ws;
    for (int i = t; i < D_IN * D_H / 4; i += 256) Ws4[i] = W4[i];

    int row0 = blockIdx.x * 32;
    // Load 32 rows of x (32 floats each) via float4: 256 float4s
    {
        int r = t / 8, f4 = t % 8;           // 8 float4 per row
        int gr = row0 + r;
        float4 v = (gr < N) ? ((const float4*)x)[(size_t)gr * 8 + f4]
                            : make_float4(0.f, 0.f, 0.f, 0.f);
        xs[r][f4 * 4 + 0] = v.x;
        xs[r][f4 * 4 + 1] = v.y;
        xs[r][f4 * 4 + 2] = v.z;
        xs[r][f4 * 4 + 3] = v.w;
    }
    __syncthreads();

    int r  = t / 8;        // row within block
    int cg = t % 8;        // column group (8 cols each)
    int row = row0 + r;
    if (row >= N) return;

    float acc[8];
    #pragma unroll
    for (int j = 0; j < 8; j++) acc[j] = 0.0f;

    #pragma unroll
    for (int k = 0; k < D_IN; k++) {
        float a = xs[r][k];
        float4 w0 = Ws4[k * 16 + cg * 2];
        float4 w1 = Ws4[k * 16 + cg * 2 + 1];
        acc[0] = fmaf(a, w0.x, acc[0]);
        acc[1] = fmaf(a, w0.y, acc[1]);
        acc[2] = fmaf(a, w0.z, acc[2]);
        acc[3] = fmaf(a, w0.w, acc[3]);
        acc[4] = fmaf(a, w1.x, acc[4]);
        acc[5] = fmaf(a, w1.y, acc[5]);
        acc[6] = fmaf(a, w1.z, acc[6]);
        acc[7] = fmaf(a, w1.w, acc[7]);
    }

    float di = g_dinv[row];
    float4* o = (float4*)(g_hs1 + (size_t)row * D_H + cg * 8);
    o[0] = make_float4(acc[0] * di, acc[1] * di, acc[2] * di, acc[3] * di);
    o[1] = make_float4(acc[4] * di, acc[5] * di, acc[6] * di, acc[7] * di);
}

// ---------------------------------------------------------------------------
// Scatter: acc[dst] += hs[src].  16 lanes/edge, float4 vector reduction.
__global__ __launch_bounds__(256) void scatter_kernel(
    const int* __restrict__ ei, int E, int N, int which)
{
    const float* hs  = (which == 1) ? g_hs1 : g_hs2;
    float*       acc = (which == 1) ? g_acc1 : g_acc2;

    long long tid = (long long)blockIdx.x * blockDim.x + threadIdx.x;
    int edge = (int)(tid >> 4);
    int lane = (int)(tid & 15);
    if (edge >= E) return;

    unsigned src = (unsigned)ei[edge];
    unsigned dst = (unsigned)ei[E + edge];
    if (src >= (unsigned)N || dst >= (unsigned)N) return;

    const float4* sp = (const float4*)(hs + (size_t)src * D_H) + lane;
    float4 v = *sp;
    float* dp = acc + (size_t)dst * D_H + lane * 4;
    asm volatile("red.global.add.v4.f32 [%0], {%1,%2,%3,%4};"
                 :: "l"(dp), "f"(v.x), "f"(v.y), "f"(v.z), "f"(v.w)
                 : "memory");
}

// ---------------------------------------------------------------------------
// Fused: h1f = relu(dinv*(acc1+hs1) + b1);  hs2 = (h1f @ W2) * dinv
// Register-tiled like gemm1: 32 rows/block, 8 threads/row × 8 cols.
__global__ __launch_bounds__(256) void gemm2_kernel(
    const float* __restrict__ W2, const float* __restrict__ b1, int N)
{
    __shared__ float Ws[D_H * D_H];      // 16 KB
    __shared__ float hsm[32][D_H];       // 8 KB (h1f rows)
    __shared__ float dis[32];

    int t = threadIdx.x;
    const float4* W4 = (const float4*)W2;
    float4* Ws4 = (float4*)Ws;
    for (int i = t; i < D_H * D_H / 4; i += 256) Ws4[i] = W4[i];

    int row0 = blockIdx.x * 32;
    // Prologue: compute h1f for 32 rows (2048 elems, 8 per thread via float4x2)
    {
        int r = t / 8, f4 = t % 8;       // f4 indexes pairs of float4 (8 floats)
        int gr = row0 + r;
        if (gr < N) {
            float di = g_dinv[gr];
            if (f4 == 0) dis[r] = di;
            size_t base = (size_t)gr * D_H + f4 * 8;
            const float4* a4 = (const float4*)(g_acc1 + base);
            const float4* h4 = (const float4*)(g_hs1 + base);
            const float4* b4 = (const float4*)(b1 + f4 * 8);
            #pragma unroll
            for (int p = 0; p < 2; p++) {
                float4 a = a4[p], h = h4[p], b = b4[p];
                hsm[r][f4 * 8 + p * 4 + 0] = fmaxf(di * (a.x + h.x) + b.x, 0.f);
                hsm[r][f4 * 8 + p * 4 + 1] = fmaxf(di * (a.y + h.y) + b.y, 0.f);
                hsm[r][f4 * 8 + p * 4 + 2] = fmaxf(di * (a.z + h.z) + b.z, 0.f);
                hsm[r][f4 * 8 + p * 4 + 3] = fmaxf(di * (a.w + h.w) + b.w, 0.f);
            }
        }
    }
    __syncthreads();

    int r  = t / 8;
    int cg = t % 8;
    int row = row0 + r;
    if (row >= N) return;

    float acc[8];
    #pragma unroll
    for (int j = 0; j < 8; j++) acc[j] = 0.0f;

    #pragma unroll 8
    for (int k = 0; k < D_H; k++) {
        float a = hsm[r][k];
        float4 w0 = Ws4[k * 16 + cg * 2];
        float4 w1 = Ws4[k * 16 + cg * 2 + 1];
        acc[0] = fmaf(a, w0.x, acc[0]);
        acc[1] = fmaf(a, w0.y, acc[1]);
        acc[2] = fmaf(a, w0.z, acc[2]);
        acc[3] = fmaf(a, w0.w, acc[3]);
        acc[4] = fmaf(a, w1.x, acc[4]);
        acc[5] = fmaf(a, w1.y, acc[5]);
        acc[6] = fmaf(a, w1.z, acc[6]);
        acc[7] = fmaf(a, w1.w, acc[7]);
    }

    float di = dis[r];
    float4* o = (float4*)(g_hs2 + (size_t)row * D_H + cg * 8);
    o[0] = make_float4(acc[0] * di, acc[1] * di, acc[2] * di, acc[3] * di);
    o[1] = make_float4(acc[4] * di, acc[5] * di, acc[6] * di, acc[7] * di);
}

// ---------------------------------------------------------------------------
// h2f = relu(dinv*(acc2+hs2) + b2);  out = sigmoid(h2f . Wo + bo)
__global__ __launch_bounds__(256) void out_kernel(
    const float* __restrict__ b2, const float* __restrict__ Wo,
    const float* __restrict__ bo, float* __restrict__ out, int N)
{
    int warp = (blockIdx.x * blockDim.x + threadIdx.x) >> 5;
    int lane = threadIdx.x & 31;
    if (warp >= N) return;

    float di = g_dinv[warp];
    size_t base = (size_t)warp * D_H;

    float s = 0.0f;
    #pragma unroll
    for (int half = 0; half < 2; half++) {
        int c = lane + half * 32;
        float h = di * (g_acc2[base + c] + g_hs2[base + c]) + b2[c];
        h = fmaxf(h, 0.0f);
        s = fmaf(h, Wo[c], s);
    }
    #pragma unroll
    for (int o = 16; o > 0; o >>= 1) s += __shfl_down_sync(0xffffffffu, s, o);

    if (lane == 0) {
        float z = s + bo[0];
        out[warp] = 1.0f / (1.0f + expf(-z));
    }
}

// ---------------------------------------------------------------------------
extern "C" void kernel_launch(void* const* d_in, const int* in_sizes, int n_in,
                              void* d_out, int out_size)
{
    const float* x  = (const float*)d_in[0];
    const int*   ei = (const int*)d_in[1];
    const float* W1 = (const float*)d_in[2];
    const float* b1 = (const float*)d_in[3];
    const float* W2 = (const float*)d_in[4];
    const float* b2 = (const float*)d_in[5];
    const float* Wo = (const float*)d_in[6];
    const float* bo = (const float*)d_in[7];
    float* out = (float*)d_out;

    int N = in_sizes[0] / D_IN;
    int E = in_sizes[1] / 2;

    zero_kernel<<<2048, 256>>>(N);
    deg_kernel<<<2048, 256>>>(ei, E, N);
    dinv_kernel<<<(N + 255) / 256, 256>>>(N);

    gemm1_kernel<<<(N + 31) / 32, 256>>>(x, W1, N);

    long long sthreads = (long long)E * 16;
    int sblocks = (int)((sthreads + 255) / 256);
    scatter_kernel<<<sblocks, 256>>>(ei, E, N, 1);

    gemm2_kernel<<<(N + 31) / 32, 256>>>(W2, b1, N);

    scatter_kernel<<<sblocks, 256>>>(ei, E, N, 2);

    out_kernel<<<(N * 32 + 255) / 256, 256>>>(b2, Wo, bo, out, N);
}